// round 1
// baseline (speedup 1.0000x reference)
#include <cuda_runtime.h>

#define FULL_MASK 0xFFFFFFFFu

constexpr int H = 512;
constexpr int W = 512;
constexpr int NPLANE = 8 * 16;          // 128 independent (B,C) planes
constexpr int STRIP_OUT = 28;           // useful output columns per 32-lane warp
constexpr int NSTRIP = (W + STRIP_OUT - 1) / STRIP_OUT;   // 19
constexpr int SEG = 128;                // output rows per warp task
constexpr int NSEG = H / SEG;           // 4
constexpr int WARPS_PER_BLOCK = 4;
constexpr int NTASK = NPLANE * NSTRIP * NSEG;             // 9728
constexpr int NBLOCK = NTASK / WARPS_PER_BLOCK;           // 2432

__global__ void __launch_bounds__(WARPS_PER_BLOCK * 32)
guided_filter_kernel(const float* __restrict__ gI,
                     const float* __restrict__ gP,
                     float* __restrict__ gO)
{
    const int lane = threadIdx.x & 31;
    const int task = blockIdx.x * WARPS_PER_BLOCK + (threadIdx.x >> 5);

    const int pl  = task / (NSTRIP * NSEG);
    const int rem = task - pl * (NSTRIP * NSEG);
    const int sx  = rem / NSEG;
    const int sy  = rem - sx * NSEG;

    // Global column for this lane (lanes 0..1 and 30..31 are halo)
    const int x = sx * STRIP_OUT - 2 + lane;
    const bool xin = ((unsigned)x < (unsigned)W);

    const size_t pbase = (size_t)pl * (size_t)(H * W);
    const float* baseI = gI + pbase;
    const float* baseP = gP + pbase;
    float*       baseO = gO + pbase;

    // Horizontal window count for this column: 3 interior, 2 at x==0 / x==W-1
    const float cxf  = (x >= 1 && x <= W - 2) ? 3.0f : 2.0f;
    const float inv3 = 1.0f / (3.0f * cxf);   // cy == 3 rows valid
    const float inv2 = 1.0f / (2.0f * cxf);   // cy == 2 rows valid (top/bottom)

    const int r0 = sy * SEG;

    // Register rings (explicit scalars -> no local-memory spill).
    // Index 2 = newest row.
    float hI0 = 0.f, hI1 = 0.f, hI2 = 0.f;       // 1x3 sums of I
    float hP0 = 0.f, hP1 = 0.f, hP2 = 0.f;       // 1x3 sums of p
    float hII0 = 0.f, hII1 = 0.f, hII2 = 0.f;    // 1x3 sums of I*I
    float hIP0 = 0.f, hIP1 = 0.f, hIP2 = 0.f;    // 1x3 sums of I*p
    float hA0 = 0.f, hA1 = 0.f, hA2 = 0.f;       // 1x3 sums of a
    float hB0 = 0.f, hB1 = 0.f, hB2 = 0.f;       // 1x3 sums of b
    float I0 = 0.f, I1 = 0.f, I2 = 0.f;          // raw I ring (need I at y-2)

    // --- step 1: load row y, build horizontal sums (rings shift, new in slot 2)
    auto step_load = [&](int it) {
        const int y = r0 - 2 + it;
        hI0 = hI1; hI1 = hI2;
        hP0 = hP1; hP1 = hP2;
        hII0 = hII1; hII1 = hII2;
        hIP0 = hIP1; hIP1 = hIP2;
        I0 = I1; I1 = I2;

        float Iv = 0.f, Pv = 0.f;
        if (xin && (unsigned)y < (unsigned)H) {
            const size_t off = (size_t)y * W + x;
            Iv = baseI[off];
            Pv = baseP[off];
        }
        const float Il = __shfl_up_sync(FULL_MASK, Iv, 1);
        const float Ir = __shfl_down_sync(FULL_MASK, Iv, 1);
        const float Pl = __shfl_up_sync(FULL_MASK, Pv, 1);
        const float Pr = __shfl_down_sync(FULL_MASK, Pv, 1);
        hI2  = Il + Iv + Ir;
        hP2  = Pl + Pv + Pr;
        hII2 = Il * Il + Iv * Iv + Ir * Ir;
        hIP2 = Il * Pl + Iv * Pv + Ir * Pr;
        I2 = Iv;
    };

    // --- step 2: finish 3x3 means centered at row y-1, compute a,b and their
    //             horizontal sums (hA/hB rings shift, new in slot 2)
    auto step_ab = [&](int it) {
        const int ry = (r0 - 2 + it) - 1;
        const float invc = (ry >= 1 && ry <= H - 2) ? inv3 : inv2;
        const float mI  = (hI0  + hI1  + hI2 ) * invc;
        const float mP  = (hP0  + hP1  + hP2 ) * invc;
        const float mII = (hII0 + hII1 + hII2) * invc;
        const float mIP = (hIP0 + hIP1 + hIP2) * invc;
        const float varI = mII - mI * mI;
        const float cov  = mIP - mI * mP;
        float a = __fdividef(cov, varI + 0.01f);
        float b = mP - a * mI;
        // Positions outside the image must contribute ZERO to the a/b blur
        // (count_include_pad=False). Halo garbage lanes also zeroed here.
        if (!(xin && (unsigned)ry < (unsigned)H)) { a = 0.f; b = 0.f; }
        const float al = __shfl_up_sync(FULL_MASK, a, 1);
        const float ar = __shfl_down_sync(FULL_MASK, a, 1);
        const float bl = __shfl_up_sync(FULL_MASK, b, 1);
        const float br = __shfl_down_sync(FULL_MASK, b, 1);
        hA0 = hA1; hA1 = hA2;
        hB0 = hB1; hB1 = hB2;
        hA2 = al + a + ar;
        hB2 = bl + b + br;
    };

    // --- step 3: finish 3x3 blur of a,b centered at row y-2, write output
    auto step_out = [&](int it) {
        const int ro = (r0 - 2 + it) - 2;
        const float invo = (ro >= 1 && ro <= H - 2) ? inv3 : inv2;
        const float mA = (hA0 + hA1 + hA2) * invo;
        const float mB = (hB0 + hB1 + hB2) * invo;
        const float o = mA * I0 + mB;     // I0 holds raw I at row ro = y-2
        if (lane >= 2 && lane <= 29 && x < W) {
            baseO[(size_t)ro * W + x] = o;
        }
    };

    // Pipeline prologue: prime rings on rows r0-2 .. r0+1
#pragma unroll
    for (int it = 0; it < 4; ++it) {
        step_load(it);
        if (it >= 2) step_ab(it);
    }
    // Steady state: each iteration loads row y, makes a,b at y-1, stores y-2
#pragma unroll 4
    for (int it = 4; it < SEG + 4; ++it) {
        step_load(it);
        step_ab(it);
        step_out(it);
    }
}

extern "C" void kernel_launch(void* const* d_in, const int* in_sizes, int n_in,
                              void* d_out, int out_size) {
    const float* I = (const float*)d_in[0];   // input
    const float* P = (const float*)d_in[1];   // guide
    float* O = (float*)d_out;
    guided_filter_kernel<<<NBLOCK, WARPS_PER_BLOCK * 32>>>(I, P, O);
}